// round 3
// baseline (speedup 1.0000x reference)
#include <cuda_runtime.h>
#include <math.h>

#define NODES 50000
#define EDGES 600000
#define DIN 128
#define DHID 256

// ---------------- device scratch (static, no allocation) ----------------
__device__ int   g_cnt[NODES];          // in-degree counts
__device__ int   g_off[NODES];          // CSR row start
__device__ int   g_cur[NODES];          // fill cursors
__device__ int   g_csrc[EDGES];         // CSR: src ids grouped by dst
__device__ __align__(16) float g_agg1[NODES * DIN];  // layer-1 mean-agg (normalized)
__device__ float2 g_t12[NODES];         // t1,t2 = h . u1/u2 (gathered in layer 2)
__device__ float2 g_w12[NODES];         // w1,w2 = h . v1/v2 (self term)
__device__ float4 g_P[DHID];            // (u1,u2,v1,v2) per hidden col
__device__ float  g_c[2];               // c1,c2 = b2l . wl_a/b
__device__ float2 g_s[NODES];           // final per-node (s1,s2)

// ---------------- zero the histogram ----------------
__global__ void k_zero() {
    int i = blockIdx.x * blockDim.x + threadIdx.x;
    if (i < NODES) g_cnt[i] = 0;
}

// ---------------- histogram of dst ----------------
__global__ void k_hist(const int* __restrict__ dst, int E) {
    int e = blockIdx.x * blockDim.x + threadIdx.x;
    if (e < E) atomicAdd(&g_cnt[dst[e]], 1);
}

// ---------------- single-block exclusive scan over 50K counts ----------------
__global__ void __launch_bounds__(1024) k_scan() {
    __shared__ int part[1024];
    const int t = threadIdx.x;
    const int per = (NODES + 1023) / 1024;  // 49
    const int base = t * per;

    int sum = 0;
    for (int i = 0; i < per; i++) {
        int n = base + i;
        if (n < NODES) sum += g_cnt[n];
    }
    part[t] = sum;
    __syncthreads();
    // Hillis-Steele inclusive scan (read phase / write phase separated)
    for (int off = 1; off < 1024; off <<= 1) {
        int u = (t >= off) ? part[t - off] : 0;
        __syncthreads();
        part[t] += u;
        __syncthreads();
    }
    int run = part[t] - sum;  // exclusive prefix for this segment
    for (int i = 0; i < per; i++) {
        int n = base + i;
        if (n < NODES) {
            g_off[n] = run;
            g_cur[n] = run;
            run += g_cnt[n];
        }
    }
}

// ---------------- CSR fill: csr_src grouped by dst ----------------
__global__ void k_fill(const int* __restrict__ src,
                       const int* __restrict__ dst, int E) {
    int e = blockIdx.x * blockDim.x + threadIdx.x;
    if (e >= E) return;
    int d = dst[e];
    int pos = atomicAdd(&g_cur[d], 1);
    g_csrc[pos] = src[e];
}

// ---------------- layer-1 mean aggregate: one warp per node, pure gather ----
__global__ void __launch_bounds__(256) k_agg1(const float* __restrict__ x) {
    int n = blockIdx.x * 8 + (threadIdx.x >> 5);
    if (n >= NODES) return;
    int lane = threadIdx.x & 31;
    int start = g_off[n], cnt = g_cnt[n];

    float4 acc = make_float4(0.f, 0.f, 0.f, 0.f);
    int j = 0;
    for (; j + 2 <= cnt; j += 2) {
        int s0 = g_csrc[start + j];
        int s1 = g_csrc[start + j + 1];
        float4 v0 = ((const float4*)(x + (size_t)s0 * DIN))[lane];
        float4 v1 = ((const float4*)(x + (size_t)s1 * DIN))[lane];
        acc.x += v0.x + v1.x; acc.y += v0.y + v1.y;
        acc.z += v0.z + v1.z; acc.w += v0.w + v1.w;
    }
    if (j < cnt) {
        int s0 = g_csrc[start + j];
        float4 v0 = ((const float4*)(x + (size_t)s0 * DIN))[lane];
        acc.x += v0.x; acc.y += v0.y; acc.z += v0.z; acc.w += v0.w;
    }
    float r = 1.0f / fmaxf((float)cnt, 1.0f);
    acc.x *= r; acc.y *= r; acc.z *= r; acc.w *= r;
    ((float4*)(g_agg1 + (size_t)n * DIN))[lane] = acc;
}

// -------- fold layer 2 + link head into 4 projection vectors --------
// u1 = W2l @ wl_a, u2 = W2l @ wl_b, v1 = W2r @ wl_a, v2 = W2r @ wl_b
__global__ void k_prep(const float* __restrict__ W2l, const float* __restrict__ W2r,
                       const float* __restrict__ Wlin, const float* __restrict__ b2l)
{
    int j = threadIdx.x;  // 0..255 hidden index
    float u1 = 0.f, u2 = 0.f, v1 = 0.f, v2 = 0.f;
    for (int k = 0; k < DIN; k++) {
        float wa = Wlin[k], wb = Wlin[DIN + k];
        float l = W2l[j * DIN + k], r = W2r[j * DIN + k];
        u1 = fmaf(l, wa, u1); u2 = fmaf(l, wb, u2);
        v1 = fmaf(r, wa, v1); v2 = fmaf(r, wb, v2);
    }
    g_P[j] = make_float4(u1, u2, v1, v2);
    if (j == 0) {
        float c1 = 0.f, c2 = 0.f;
        for (int k = 0; k < DIN; k++) {
            c1 = fmaf(b2l[k], Wlin[k], c1);
            c2 = fmaf(b2l[k], Wlin[DIN + k], c2);
        }
        g_c[0] = c1; g_c[1] = c2;
    }
}

// -------- fused layer-1 GEMM + relu + 4-vector projection epilogue --------
// z[n, 0:256] = [agg1[n], x[n]] @ [W1l ; W1r] + b1l ; h = relu(z)
// outputs t12[n] = (h.u1, h.u2), w12[n] = (h.v1, h.v2)
__global__ void __launch_bounds__(256) k_l1(
    const float* __restrict__ x,
    const float* __restrict__ W1l, const float* __restrict__ W1r,
    const float* __restrict__ b1l)
{
    extern __shared__ float sm[];
    float* sx = sm;             // 64 x 256 input tile
    float* sw = sm + 64 * 256;  // 32 x 256 weight K-chunk

    const int tid = threadIdx.x;
    const int node0 = blockIdx.x * 64;

    // stage input tile: cols 0..127 = agg1 (pre-normalized), cols 128..255 = x
    for (int i = tid; i < 64 * 64; i += 256) {
        int n = i >> 6, q = i & 63;
        int gn = node0 + n;
        float4 v = make_float4(0.f, 0.f, 0.f, 0.f);
        if (gn < NODES) {
            if (q < 32) v = ((const float4*)(g_agg1 + (size_t)gn * DIN))[q];
            else        v = ((const float4*)(x      + (size_t)gn * DIN))[q - 32];
        }
        ((float4*)(sx + n * 256))[q] = v;
    }

    const int warp = tid >> 5, lane = tid & 31;
    float acc[8][8];
#pragma unroll
    for (int a = 0; a < 8; a++)
#pragma unroll
        for (int b = 0; b < 8; b++) acc[a][b] = 0.f;

    for (int kc = 0; kc < 256; kc += 32) {
        __syncthreads();
        for (int i = tid; i < 32 * 64; i += 256) {
            int kk = i >> 6, q = i & 63;
            int k = kc + kk;
            const float4* Wrow = (k < 128)
                ? (const float4*)(W1l + (size_t)k * 256)
                : (const float4*)(W1r + (size_t)(k - 128) * 256);
            ((float4*)(sw + kk * 256))[q] = Wrow[q];
        }
        __syncthreads();
#pragma unroll
        for (int kk = 0; kk < 32; kk += 4) {
            float4 xv[8];
#pragma unroll
            for (int nn = 0; nn < 8; nn++)
                xv[nn] = *((const float4*)(sx + (warp * 8 + nn) * 256 + kc + kk));
#pragma unroll
            for (int dk = 0; dk < 4; dk++) {
                float4 wa = *((const float4*)(sw + (kk + dk) * 256 + lane * 4));
                float4 wb = *((const float4*)(sw + (kk + dk) * 256 + 128 + lane * 4));
#pragma unroll
                for (int nn = 0; nn < 8; nn++) {
                    float xs = (dk == 0) ? xv[nn].x : (dk == 1) ? xv[nn].y
                             : (dk == 2) ? xv[nn].z : xv[nn].w;
                    acc[nn][0] = fmaf(xs, wa.x, acc[nn][0]);
                    acc[nn][1] = fmaf(xs, wa.y, acc[nn][1]);
                    acc[nn][2] = fmaf(xs, wa.z, acc[nn][2]);
                    acc[nn][3] = fmaf(xs, wa.w, acc[nn][3]);
                    acc[nn][4] = fmaf(xs, wb.x, acc[nn][4]);
                    acc[nn][5] = fmaf(xs, wb.y, acc[nn][5]);
                    acc[nn][6] = fmaf(xs, wb.z, acc[nn][6]);
                    acc[nn][7] = fmaf(xs, wb.w, acc[nn][7]);
                }
            }
        }
    }

    // epilogue: bias + relu + project onto (u1,u2,v1,v2), warp-reduce per node
    const int cA = lane * 4, cB = 128 + lane * 4;
    float4 bA = *((const float4*)(b1l + cA));
    float4 bB = *((const float4*)(b1l + cB));
    float4 PA0 = g_P[cA], PA1 = g_P[cA + 1], PA2 = g_P[cA + 2], PA3 = g_P[cA + 3];
    float4 PB0 = g_P[cB], PB1 = g_P[cB + 1], PB2 = g_P[cB + 2], PB3 = g_P[cB + 3];

#pragma unroll
    for (int nn = 0; nn < 8; nn++) {
        float h0 = fmaxf(acc[nn][0] + bA.x, 0.f);
        float h1 = fmaxf(acc[nn][1] + bA.y, 0.f);
        float h2 = fmaxf(acc[nn][2] + bA.z, 0.f);
        float h3 = fmaxf(acc[nn][3] + bA.w, 0.f);
        float h4 = fmaxf(acc[nn][4] + bB.x, 0.f);
        float h5 = fmaxf(acc[nn][5] + bB.y, 0.f);
        float h6 = fmaxf(acc[nn][6] + bB.z, 0.f);
        float h7 = fmaxf(acc[nn][7] + bB.w, 0.f);
        float t1 = h0*PA0.x + h1*PA1.x + h2*PA2.x + h3*PA3.x
                 + h4*PB0.x + h5*PB1.x + h6*PB2.x + h7*PB3.x;
        float t2 = h0*PA0.y + h1*PA1.y + h2*PA2.y + h3*PA3.y
                 + h4*PB0.y + h5*PB1.y + h6*PB2.y + h7*PB3.y;
        float w1 = h0*PA0.z + h1*PA1.z + h2*PA2.z + h3*PA3.z
                 + h4*PB0.z + h5*PB1.z + h6*PB2.z + h7*PB3.z;
        float w2 = h0*PA0.w + h1*PA1.w + h2*PA2.w + h3*PA3.w
                 + h4*PB0.w + h5*PB1.w + h6*PB2.w + h7*PB3.w;
#pragma unroll
        for (int off = 16; off > 0; off >>= 1) {
            t1 += __shfl_xor_sync(0xffffffffu, t1, off);
            t2 += __shfl_xor_sync(0xffffffffu, t2, off);
            w1 += __shfl_xor_sync(0xffffffffu, w1, off);
            w2 += __shfl_xor_sync(0xffffffffu, w2, off);
        }
        if (lane == 0) {
            int gn = node0 + warp * 8 + nn;
            if (gn < NODES) {
                g_t12[gn] = make_float2(t1, t2);
                g_w12[gn] = make_float2(w1, w2);
            }
        }
    }
}

// -------- layer-2 aggregate (gather) + finalize: s = mean(t12) + w + c ------
__global__ void k_fin() {
    int n = blockIdx.x * blockDim.x + threadIdx.x;
    if (n >= NODES) return;
    int start = g_off[n], cnt = g_cnt[n];
    float a1 = 0.f, a2 = 0.f;
    for (int j = 0; j < cnt; j++) {
        float2 t = g_t12[g_csrc[start + j]];
        a1 += t.x; a2 += t.y;
    }
    float r = 1.0f / fmaxf((float)cnt, 1.0f);
    float2 w = g_w12[n];
    g_s[n] = make_float2(a1 * r + w.x + g_c[0],
                         a2 * r + w.y + g_c[1]);
}

// -------- pair head: sigmoid(s1[i] + s2[j] + blin) --------
__global__ void k_pairs(const int* __restrict__ mask,
                        const float* __restrict__ blin,
                        float* __restrict__ out, int P)
{
    int p = blockIdx.x * blockDim.x + threadIdx.x;
    if (p >= P) return;
    int i = mask[2 * p], j = mask[2 * p + 1];
    float z = g_s[i].x + g_s[j].y + blin[0];
    out[p] = 1.0f / (1.0f + expf(-z));
}

// ---------------- launch ----------------
extern "C" void kernel_launch(void* const* d_in, const int* in_sizes, int n_in,
                              void* d_out, int out_size)
{
    const float* x    = (const float*)d_in[0];
    const int*   ei   = (const int*)d_in[1];     // int32 (JAX x64 disabled)
    const int*   mask = (const int*)d_in[2];     // int32
    const float* W1l  = (const float*)d_in[3];
    const float* b1l  = (const float*)d_in[4];
    const float* W1r  = (const float*)d_in[5];
    const float* W2l  = (const float*)d_in[6];
    const float* b2l  = (const float*)d_in[7];
    const float* W2r  = (const float*)d_in[8];
    const float* Wlin = (const float*)d_in[9];
    const float* blin = (const float*)d_in[10];
    float* out = (float*)d_out;

    int E = in_sizes[1] / 2;   // edge_index is [2, E]
    int P = in_sizes[2] / 2;   // mask is [P, 2]
    const int* src = ei;
    const int* dst = ei + E;

    const int SMEM = (64 * 256 + 32 * 256) * sizeof(float);  // 96 KB
    cudaFuncSetAttribute((const void*)k_l1,
                         cudaFuncAttributeMaxDynamicSharedMemorySize, SMEM);

    k_zero<<<(NODES + 255) / 256, 256>>>();
    k_hist<<<(E + 255) / 256, 256>>>(dst, E);
    k_scan<<<1, 1024>>>();
    k_fill<<<(E + 255) / 256, 256>>>(src, dst, E);
    k_prep<<<1, 256>>>(W2l, W2r, Wlin, b2l);
    k_agg1<<<(NODES + 7) / 8, 256>>>(x);
    k_l1<<<(NODES + 63) / 64, 256, SMEM>>>(x, W1l, W1r, b1l);
    k_fin<<<(NODES + 255) / 256, 256>>>();
    k_pairs<<<(P + 255) / 256, 256>>>(mask, blin, out, P);
}